// round 7
// baseline (speedup 1.0000x reference)
#include <cuda_runtime.h>
#include <cuda_bf16.h>

// ---------------------------------------------------------------------------
// QCNNHybrid R6: ONE persistent kernel.
//  Phase A: cp.async.bulk double-buffered 16KB chunks -> SMEM reduce (stats).
//  Handshake: atomic ticket; last CTA folds BN into layer-1 and publishes
//             duplicated f32x2 params; release/acquire generation flag.
//  Phase B: grid-stride main loop, 2 packs (4 rows)/thread, LDS.128 weights.
// ---------------------------------------------------------------------------

#define GRID       444          // 148 SM x 3 CTAs, guaranteed resident
#define NT         128
#define NCHUNK     2048         // 2048 x 16KB = 32MB = whole x
#define CHUNK_ROWS 512

typedef unsigned long long u64;

__device__ float g_partials[GRID * 16];
__device__ unsigned int g_ticket;   // zero-init
__device__ unsigned int g_gen;      // zero-init, monotonic across replays

// layout B (u64 units): per layer [bias x DOUT][weights j-major: DOUT x DIN]
#define FM_B 0
#define FM_W 16
#define C1_B 144
#define C1_W 160
#define P1_B 416
#define P1_W 428
#define C2_B 620
#define C2_W 628
#define P2_B 724
#define P2_W 728
#define C3_B 760
#define C3_W 764
#define R_B  780
#define R_W  784
#define H_B  800
#define H_W  801
#define U_TOTAL 805
__device__ float2 g_w[U_TOTAL];

// ------------------------------- helpers -----------------------------------
__device__ __forceinline__ u64 pk2(float a, float b) {
    u64 r;
    asm("mov.b64 %0,{%1,%2};" : "=l"(r) : "f"(a), "f"(b));
    return r;
}
__device__ __forceinline__ void upk2(u64 v, float& a, float& b) {
    asm("mov.b64 {%0,%1},%2;" : "=f"(a), "=f"(b) : "l"(v));
}
__device__ __forceinline__ u64 ffma2(u64 a, u64 b, u64 c) {
    u64 d;
    asm("fma.rn.f32x2 %0,%1,%2,%3;" : "=l"(d) : "l"(a), "l"(b), "l"(c));
    return d;
}
__device__ __forceinline__ u64 fadd2(u64 a, u64 b) {
    u64 d;
    asm("add.rn.f32x2 %0,%1,%2;" : "=l"(d) : "l"(a), "l"(b));
    return d;
}
__device__ __forceinline__ float tanh_ap(float x) {
    float y;
    asm("tanh.approx.f32 %0,%1;" : "=f"(y) : "f"(x));
    return y;
}
__device__ __forceinline__ u64 tanh2(u64 v) {
    float a, b;
    upk2(v, a, b);
    return pk2(tanh_ap(a), tanh_ap(b));
}
__device__ __forceinline__ u64 relu2(u64 v) {
    float a, b;
    upk2(v, a, b);
    return pk2(fmaxf(a, 0.0f), fmaxf(b, 0.0f));
}
__device__ __forceinline__ unsigned smem_u32(const void* p) {
    return (unsigned)__cvta_generic_to_shared(p);
}
__device__ __forceinline__ unsigned ld_acquire(const unsigned int* p) {
    unsigned v;
    asm volatile("ld.acquire.gpu.global.b32 %0,[%1];" : "=r"(v) : "l"(p));
    return v;
}
__device__ __forceinline__ void st_release(unsigned int* p, unsigned v) {
    asm volatile("st.release.gpu.global.b32 [%0],%1;" :: "l"(p), "r"(v) : "memory");
}

// dense layer on two packs (4 rows); weight pairs via aligned LDS.128
template <int DIN, int DOUT, int BB, int WB, bool ACT>
__device__ __forceinline__ void layer2P(const u64* __restrict__ sw,
                                        const u64* __restrict__ a0,
                                        const u64* __restrict__ a1,
                                        u64* __restrict__ o0,
                                        u64* __restrict__ o1) {
#pragma unroll
    for (int j = 0; j < DOUT; j++) {
        u64 acc0 = sw[BB + j];
        u64 acc1 = acc0;
#pragma unroll
        for (int i = 0; i < DIN; i += 2) {
            ulonglong2 w = *(const ulonglong2*)(sw + WB + j * DIN + i);
            acc0 = ffma2(a0[i], w.x, acc0);
            acc1 = ffma2(a1[i], w.x, acc1);
            acc0 = ffma2(a0[i + 1], w.y, acc0);
            acc1 = ffma2(a1[i + 1], w.y, acc1);
        }
        if (ACT) { acc0 = tanh2(acc0); acc1 = tanh2(acc1); }
        o0[j] = acc0;
        o1[j] = acc1;
    }
}

// ------------------------------- the kernel --------------------------------
__global__ void __launch_bounds__(NT, 3) k_all(
    const float* __restrict__ x,
    const float* __restrict__ bn_g, const float* __restrict__ bn_b,
    const float* __restrict__ w_fm, const float* __restrict__ b_fm,
    const float* __restrict__ w_c1, const float* __restrict__ b_c1,
    const float* __restrict__ w_p1, const float* __restrict__ b_p1,
    const float* __restrict__ w_c2, const float* __restrict__ b_c2,
    const float* __restrict__ w_p2, const float* __restrict__ b_p2,
    const float* __restrict__ w_c3, const float* __restrict__ b_c3,
    const float* __restrict__ w_r,  const float* __restrict__ b_r,
    const float* __restrict__ w_h,  const float* __restrict__ b_h,
    float* __restrict__ out, float invB, int nrows) {
    __shared__ __align__(16) float s_buf[2][CHUNK_ROWS * 8];   // 2 x 16KB
    __shared__ __align__(8) u64 s_mbar[2];
    __shared__ float s_red[4][16];
    __shared__ float s1[128];
    __shared__ float totals[16];
    __shared__ float scale[8], shift[8];
    __shared__ int s_last;
    __shared__ __align__(16) u64 sw[U_TOTAL + 1];

    const int tid = threadIdx.x;
    const int cta = blockIdx.x;
    const unsigned g0 = *(volatile unsigned*)&g_gen;   // read BEFORE any ticketing

    // ============================ Phase A: stats ===========================
    unsigned mb[2] = { smem_u32(&s_mbar[0]), smem_u32(&s_mbar[1]) };
    unsigned sb[2] = { smem_u32(s_buf[0]), smem_u32(s_buf[1]) };
    if (tid == 0) {
        asm volatile("mbarrier.init.shared.b64 [%0], 1;" :: "r"(mb[0]) : "memory");
        asm volatile("mbarrier.init.shared.b64 [%0], 1;" :: "r"(mb[1]) : "memory");
        asm volatile("fence.proxy.async.shared::cta;" ::: "memory");
    }
    __syncthreads();

    const int nmine = (NCHUNK - cta + GRID - 1) / GRID;   // 4 or 5 chunks
#define ISSUE_COPY(k)                                                          \
    do {                                                                       \
        int _b = (k) & 1;                                                      \
        const char* _src = (const char*)x + (size_t)(cta + (k) * GRID) * 16384;\
        asm volatile("mbarrier.arrive.expect_tx.shared.b64 _, [%0], %1;"       \
                     :: "r"(mb[_b]), "r"(16384u) : "memory");                  \
        asm volatile(                                                          \
            "cp.async.bulk.shared::cluster.global.mbarrier::complete_tx::bytes "\
            "[%0], [%1], %2, [%3];"                                            \
            :: "r"(sb[_b]), "l"(_src), "r"(16384u), "r"(mb[_b]) : "memory");   \
    } while (0)

    if (tid == 0) {
        ISSUE_COPY(0);
        if (nmine > 1) ISSUE_COPY(1);
    }

    float s[8], q[8];
#pragma unroll
    for (int c = 0; c < 8; c++) { s[c] = 0.0f; q[c] = 0.0f; }

    for (int k = 0; k < nmine; k++) {
        int b = k & 1, parity = (k >> 1) & 1;
        asm volatile(
            "{\n\t"
            ".reg .pred p;\n\t"
            "WAITA_%=:\n\t"
            "mbarrier.try_wait.parity.acquire.cta.shared::cta.b64 p, [%0], %1;\n\t"
            "@!p bra WAITA_%=;\n\t"
            "}"
            :: "r"(mb[b]), "r"(parity) : "memory");
        // conflict-free column-strided read: thread t handles rows t, t+128, ...
        const float4* sv = (const float4*)s_buf[b];
#pragma unroll
        for (int r = 0; r < 4; r++) {
            float4 a = sv[(tid + r * 128) * 2];
            float4 bb = sv[(tid + r * 128) * 2 + 1];
            s[0] += a.x;  q[0] = fmaf(a.x, a.x, q[0]);
            s[1] += a.y;  q[1] = fmaf(a.y, a.y, q[1]);
            s[2] += a.z;  q[2] = fmaf(a.z, a.z, q[2]);
            s[3] += a.w;  q[3] = fmaf(a.w, a.w, q[3]);
            s[4] += bb.x; q[4] = fmaf(bb.x, bb.x, q[4]);
            s[5] += bb.y; q[5] = fmaf(bb.y, bb.y, q[5]);
            s[6] += bb.z; q[6] = fmaf(bb.z, bb.z, q[6]);
            s[7] += bb.w; q[7] = fmaf(bb.w, bb.w, q[7]);
        }
        __syncthreads();                   // buffer fully consumed
        if (tid == 0 && k + 2 < nmine) ISSUE_COPY(k + 2);
    }

#pragma unroll
    for (int c = 0; c < 8; c++) {
#pragma unroll
        for (int o = 16; o > 0; o >>= 1) {
            s[c] += __shfl_xor_sync(0xffffffffu, s[c], o);
            q[c] += __shfl_xor_sync(0xffffffffu, q[c], o);
        }
    }
    int warp = tid >> 5, lane = tid & 31;
    if (lane == 0) {
#pragma unroll
        for (int c = 0; c < 8; c++) { s_red[warp][c] = s[c]; s_red[warp][8 + c] = q[c]; }
    }
    __syncthreads();
    if (tid == 0) {
#pragma unroll
        for (int c = 0; c < 16; c++) {
            float acc = s_red[0][c] + s_red[1][c] + s_red[2][c] + s_red[3][c];
            g_partials[cta * 16 + c] = acc;
        }
        __threadfence();
        s_last = (atomicAdd(&g_ticket, 1u) == (unsigned)(GRID - 1));
    }
    __syncthreads();

    // ============================ Fold (last CTA) ==========================
    if (s_last) {
        {   // 16 cols x 8 chunks of 56
            int col = tid & 15, chunk = tid >> 4;
            int b0 = chunk * 56;
            int b1 = b0 + 56; if (b1 > GRID) b1 = GRID;
            float a0 = 0, a1 = 0, a2 = 0, a3 = 0;
            for (int b = b0; b + 3 < b1; b += 4) {
                a0 += g_partials[(b + 0) * 16 + col];
                a1 += g_partials[(b + 1) * 16 + col];
                a2 += g_partials[(b + 2) * 16 + col];
                a3 += g_partials[(b + 3) * 16 + col];
            }
            s1[col * 8 + chunk] = (a0 + a1) + (a2 + a3);
        }
        __syncthreads();
        if (tid < 16) {
            float acc = 0.0f;
#pragma unroll
            for (int k = 0; k < 8; k++) acc += s1[tid * 8 + k];
            totals[tid] = acc;
        }
        __syncthreads();
        if (tid < 8) {
            float mu = totals[tid] * invB;
            float var = totals[8 + tid] * invB - mu * mu;
            float sc = bn_g[tid] * rsqrtf(var + 1e-5f);
            scale[tid] = sc;
            shift[tid] = bn_b[tid] - mu * sc;
        }
        __syncthreads();
        // folded first layer
        if (tid < 16) {
            float v = b_fm[tid];
#pragma unroll
            for (int i = 0; i < 8; i++) v += shift[i] * w_fm[i * 16 + tid];
            g_w[FM_B + tid] = make_float2(v, v);
        }
        {   // 128 weights, exactly 128 threads
            int j = tid >> 3, i = tid & 7;
            float v = scale[i] * w_fm[i * 16 + j];
            g_w[FM_W + j * 8 + i] = make_float2(v, v);
        }
        for (int idx = tid; idx < 256; idx += NT) {        // c1 16->16
            int j = idx >> 4, i = idx & 15;
            float v = w_c1[i * 16 + j];
            g_w[C1_W + j * 16 + i] = make_float2(v, v);
        }
        if (tid < 16) { float v = b_c1[tid]; g_w[C1_B + tid] = make_float2(v, v); }
        for (int idx = tid; idx < 192; idx += NT) {        // p1 16->12
            int j = idx >> 4, i = idx & 15;
            float v = w_p1[i * 12 + j];
            g_w[P1_W + j * 16 + i] = make_float2(v, v);
        }
        if (tid < 12) { float v = b_p1[tid]; g_w[P1_B + tid] = make_float2(v, v); }
        if (tid < 96) {                                    // c2 12->8
            int j = tid / 12, i = tid % 12;
            float v = w_c2[i * 8 + j];
            g_w[C2_W + j * 12 + i] = make_float2(v, v);
        }
        if (tid < 8) { float v = b_c2[tid]; g_w[C2_B + tid] = make_float2(v, v); }
        if (tid < 32) {                                    // p2 8->4
            int j = tid >> 3, i = tid & 7;
            float v = w_p2[i * 4 + j];
            g_w[P2_W + j * 8 + i] = make_float2(v, v);
        }
        if (tid < 4) { float v = b_p2[tid]; g_w[P2_B + tid] = make_float2(v, v); }
        if (tid < 16) {                                    // c3 4->4
            int j = tid >> 2, i = tid & 3;
            float v = w_c3[i * 4 + j];
            g_w[C3_W + j * 4 + i] = make_float2(v, v);
        }
        if (tid < 4) { float v = b_c3[tid]; g_w[C3_B + tid] = make_float2(v, v); }
        if (tid < 16) {                                    // r 4->4
            int j = tid >> 2, i = tid & 3;
            float v = w_r[i * 4 + j];
            g_w[R_W + j * 4 + i] = make_float2(v, v);
        }
        if (tid < 4) { float v = b_r[tid]; g_w[R_B + tid] = make_float2(v, v); }
        if (tid < 4) { float v = w_h[tid]; g_w[H_W + tid] = make_float2(v, v); }
        if (tid == 0) { float v = b_h[0]; g_w[H_B] = make_float2(v, v); }
        __threadfence();
        __syncthreads();
        if (tid == 0) {
            g_ticket = 0;                  // reset for next replay
            __threadfence();
            st_release(&g_gen, g0 + 1);    // publish
        }
    }

    // ============================ Spin handshake ===========================
    while (ld_acquire(&g_gen) == g0) __nanosleep(64);

    // ============================ Phase B: main ============================
    for (int i = tid; i < U_TOTAL; i += NT) sw[i] = ((const u64*)g_w)[i];
    __syncthreads();

    const int npacks = nrows >> 2;                        // 4-row packs
    for (int p = cta * NT + tid; p < npacks; p += GRID * NT) {
        const float4* xv = (const float4*)(x + (size_t)p * 32);
        float4 r0a = xv[0], r0b = xv[1];
        float4 r1a = xv[2], r1b = xv[3];
        float4 r2a = xv[4], r2b = xv[5];
        float4 r3a = xv[6], r3b = xv[7];

        u64 A0[16], A1[16], B0[16], B1[16];
        A0[0] = pk2(r0a.x, r1a.x); A1[0] = pk2(r2a.x, r3a.x);
        A0[1] = pk2(r0a.y, r1a.y); A1[1] = pk2(r2a.y, r3a.y);
        A0[2] = pk2(r0a.z, r1a.z); A1[2] = pk2(r2a.z, r3a.z);
        A0[3] = pk2(r0a.w, r1a.w); A1[3] = pk2(r2a.w, r3a.w);
        A0[4] = pk2(r0b.x, r1b.x); A1[4] = pk2(r2b.x, r3b.x);
        A0[5] = pk2(r0b.y, r1b.y); A1[5] = pk2(r2b.y, r3b.y);
        A0[6] = pk2(r0b.z, r1b.z); A1[6] = pk2(r2b.z, r3b.z);
        A0[7] = pk2(r0b.w, r1b.w); A1[7] = pk2(r2b.w, r3b.w);

        layer2P<8, 16, FM_B, FM_W, true>(sw, A0, A1, B0, B1);
        layer2P<16, 16, C1_B, C1_W, true>(sw, B0, B1, A0, A1);
        layer2P<16, 12, P1_B, P1_W, true>(sw, A0, A1, B0, B1);
        layer2P<12, 8, C2_B, C2_W, true>(sw, B0, B1, A0, A1);
        layer2P<8, 4, P2_B, P2_W, true>(sw, A0, A1, B0, B1);
        layer2P<4, 4, C3_B, C3_W, true>(sw, B0, B1, A0, A1);
        layer2P<4, 4, R_B, R_W, false>(sw, A0, A1, B0, B1);
#pragma unroll
        for (int j = 0; j < 4; j++) {
            A0[j] = fadd2(A0[j], relu2(B0[j]));
            A1[j] = fadd2(A1[j], relu2(B1[j]));
        }

        u64 acc0 = sw[H_B], acc1 = acc0;
#pragma unroll
        for (int i = 0; i < 4; i++) {
            u64 w = sw[H_W + i];
            acc0 = ffma2(A0[i], w, acc0);
            acc1 = ffma2(A1[i], w, acc1);
        }
        float z0, z1, z2, z3;
        upk2(acc0, z0, z1);
        upk2(acc1, z2, z3);
        float4 o;
        o.x = fmaf(0.5f, tanh_ap(0.5f * z0), 0.5f);
        o.y = fmaf(0.5f, tanh_ap(0.5f * z1), 0.5f);
        o.z = fmaf(0.5f, tanh_ap(0.5f * z2), 0.5f);
        o.w = fmaf(0.5f, tanh_ap(0.5f * z3), 0.5f);
        ((float4*)out)[p] = o;
    }
}

// ------------------------------- launch ------------------------------------
extern "C" void kernel_launch(void* const* d_in, const int* in_sizes, int n_in,
                              void* d_out, int out_size) {
    const float* x    = (const float*)d_in[0];
    const float* bn_g = (const float*)d_in[1];
    const float* bn_b = (const float*)d_in[2];
    const float* w_fm = (const float*)d_in[3];
    const float* b_fm = (const float*)d_in[4];
    const float* w_c1 = (const float*)d_in[5];
    const float* b_c1 = (const float*)d_in[6];
    const float* w_p1 = (const float*)d_in[7];
    const float* b_p1 = (const float*)d_in[8];
    const float* w_c2 = (const float*)d_in[9];
    const float* b_c2 = (const float*)d_in[10];
    const float* w_p2 = (const float*)d_in[11];
    const float* b_p2 = (const float*)d_in[12];
    const float* w_c3 = (const float*)d_in[13];
    const float* b_c3 = (const float*)d_in[14];
    const float* w_r  = (const float*)d_in[15];
    const float* b_r  = (const float*)d_in[16];
    const float* w_h  = (const float*)d_in[17];
    const float* b_h  = (const float*)d_in[18];
    float* out = (float*)d_out;

    int nrows = in_sizes[0] / 8;                      // 1048576

    k_all<<<GRID, NT>>>(x, bn_g, bn_b, w_fm, b_fm, w_c1, b_c1, w_p1, b_p1,
                        w_c2, b_c2, w_p2, b_p2, w_c3, b_c3, w_r, b_r,
                        w_h, b_h, out, 1.0f / (float)nrows, nrows);
}

// round 8
// speedup vs baseline: 5.4403x; 5.4403x over previous
#include <cuda_runtime.h>
#include <cuda_bf16.h>

// ---------------------------------------------------------------------------
// QCNNHybrid R7 (base = R4 two-kernel):
//  k_statsfold : pinned MLP=8 LDG4s; SMEM-transpose reduction (replaces 80
//                SHFL/thread); last block (ticket) folds BN, publishes params.
//  k_main      : R4 core (2 packs / 4 rows per thread, LDS.128 weight pairs)
//                with launch_bounds(128,4) -> 128 regs, 16 warps/SM.
// ---------------------------------------------------------------------------

#define NBLK_STATS 1024
#define NT_STATS   256
#define NT_MAIN    128

__device__ float g_partials[NBLK_STATS * 16];
__device__ unsigned int g_ticket;

// layout B (u64 units): per layer [bias x DOUT][weights j-major: DOUT x DIN]
#define FM_B 0
#define FM_W 16     // 16 + 128 = 144
#define C1_B 144
#define C1_W 160    // + 256 = 416
#define P1_B 416
#define P1_W 428    // + 192 = 620
#define C2_B 620
#define C2_W 628    // + 96 = 724
#define P2_B 724
#define P2_W 728    // + 32 = 760
#define C3_B 760
#define C3_W 764    // + 16 = 780
#define R_B  780
#define R_W  784    // + 16 = 800
#define H_B  800
#define H_W  801    // + 4 = 805
#define U_TOTAL 805
__device__ float2 g_w[U_TOTAL];

typedef unsigned long long u64;

// ------------------------------- f32x2 helpers -----------------------------
__device__ __forceinline__ u64 pk2(float a, float b) {
    u64 r;
    asm("mov.b64 %0,{%1,%2};" : "=l"(r) : "f"(a), "f"(b));
    return r;
}
__device__ __forceinline__ void upk2(u64 v, float& a, float& b) {
    asm("mov.b64 {%0,%1},%2;" : "=f"(a), "=f"(b) : "l"(v));
}
__device__ __forceinline__ u64 ffma2(u64 a, u64 b, u64 c) {
    u64 d;
    asm("fma.rn.f32x2 %0,%1,%2,%3;" : "=l"(d) : "l"(a), "l"(b), "l"(c));
    return d;
}
__device__ __forceinline__ u64 fadd2(u64 a, u64 b) {
    u64 d;
    asm("add.rn.f32x2 %0,%1,%2;" : "=l"(d) : "l"(a), "l"(b));
    return d;
}
__device__ __forceinline__ float tanh_ap(float x) {
    float y;
    asm("tanh.approx.f32 %0,%1;" : "=f"(y) : "f"(x));
    return y;
}
__device__ __forceinline__ u64 tanh2(u64 v) {
    float a, b;
    upk2(v, a, b);
    return pk2(tanh_ap(a), tanh_ap(b));
}
__device__ __forceinline__ u64 relu2(u64 v) {
    float a, b;
    upk2(v, a, b);
    return pk2(fmaxf(a, 0.0f), fmaxf(b, 0.0f));
}

// dense layer on two packs (4 rows). Weight pairs fetched as aligned LDS.128.
template <int DIN, int DOUT, int BB, int WB, bool ACT>
__device__ __forceinline__ void layer2P(const u64* __restrict__ sw,
                                        const u64* __restrict__ a0,
                                        const u64* __restrict__ a1,
                                        u64* __restrict__ o0,
                                        u64* __restrict__ o1) {
#pragma unroll
    for (int j = 0; j < DOUT; j++) {
        u64 acc0 = sw[BB + j];                        // duplicated bias
        u64 acc1 = acc0;
#pragma unroll
        for (int i = 0; i < DIN; i += 2) {
            ulonglong2 w = *(const ulonglong2*)(sw + WB + j * DIN + i);
            acc0 = ffma2(a0[i], w.x, acc0);
            acc1 = ffma2(a1[i], w.x, acc1);
            acc0 = ffma2(a0[i + 1], w.y, acc0);
            acc1 = ffma2(a1[i + 1], w.y, acc1);
        }
        if (ACT) { acc0 = tanh2(acc0); acc1 = tanh2(acc1); }
        o0[j] = acc0;
        o1[j] = acc1;
    }
}

#define LDG4(dst, ptr)                                                        \
    asm volatile("ld.global.nc.v4.f32 {%0,%1,%2,%3},[%4];"                    \
                 : "=f"(dst.x), "=f"(dst.y), "=f"(dst.z), "=f"(dst.w)         \
                 : "l"(ptr))

// --------------------------- kernel A: stats + fold ------------------------
#define TPAD 264   // 256 + 8 pad, channel-major transpose buffer row length

__global__ void __launch_bounds__(NT_STATS) k_statsfold(
    const float* __restrict__ x,
    const float* __restrict__ bn_g, const float* __restrict__ bn_b,
    const float* __restrict__ w_fm, const float* __restrict__ b_fm,
    const float* __restrict__ w_c1, const float* __restrict__ b_c1,
    const float* __restrict__ w_p1, const float* __restrict__ b_p1,
    const float* __restrict__ w_c2, const float* __restrict__ b_c2,
    const float* __restrict__ w_p2, const float* __restrict__ b_p2,
    const float* __restrict__ w_c3, const float* __restrict__ b_c3,
    const float* __restrict__ w_r,  const float* __restrict__ b_r,
    const float* __restrict__ w_h,  const float* __restrict__ b_h,
    float invB, int nrows) {
    __shared__ __align__(16) float s_t[16 * TPAD];    // ~16.5 KB transpose buf
    int tid = threadIdx.x;
    int g = blockIdx.x * NT_STATS + tid;
    long base = (long)g * 4;                          // 4 rows / thread
    float s[8], q[8];
    {
        const float4* xv = (const float4*)(x + base * 8);
        float4 v0, v1, v2, v3, v4, v5, v6, v7;
        LDG4(v0, xv + 0); LDG4(v1, xv + 1);
        LDG4(v2, xv + 2); LDG4(v3, xv + 3);
        LDG4(v4, xv + 4); LDG4(v5, xv + 5);
        LDG4(v6, xv + 6); LDG4(v7, xv + 7);
        s[0] = v0.x + v2.x + v4.x + v6.x;
        s[1] = v0.y + v2.y + v4.y + v6.y;
        s[2] = v0.z + v2.z + v4.z + v6.z;
        s[3] = v0.w + v2.w + v4.w + v6.w;
        s[4] = v1.x + v3.x + v5.x + v7.x;
        s[5] = v1.y + v3.y + v5.y + v7.y;
        s[6] = v1.z + v3.z + v5.z + v7.z;
        s[7] = v1.w + v3.w + v5.w + v7.w;
        q[0] = fmaf(v0.x, v0.x, fmaf(v2.x, v2.x, fmaf(v4.x, v4.x, v6.x * v6.x)));
        q[1] = fmaf(v0.y, v0.y, fmaf(v2.y, v2.y, fmaf(v4.y, v4.y, v6.y * v6.y)));
        q[2] = fmaf(v0.z, v0.z, fmaf(v2.z, v2.z, fmaf(v4.z, v4.z, v6.z * v6.z)));
        q[3] = fmaf(v0.w, v0.w, fmaf(v2.w, v2.w, fmaf(v4.w, v4.w, v6.w * v6.w)));
        q[4] = fmaf(v1.x, v1.x, fmaf(v3.x, v3.x, fmaf(v5.x, v5.x, v7.x * v7.x)));
        q[5] = fmaf(v1.y, v1.y, fmaf(v3.y, v3.y, fmaf(v5.y, v5.y, v7.y * v7.y)));
        q[6] = fmaf(v1.z, v1.z, fmaf(v3.z, v3.z, fmaf(v5.z, v5.z, v7.z * v7.z)));
        q[7] = fmaf(v1.w, v1.w, fmaf(v3.w, v3.w, fmaf(v5.w, v5.w, v7.w * v7.w)));
    }
    // transpose into channel-major smem: channel c row = s_t[c*TPAD + tid]
#pragma unroll
    for (int c = 0; c < 8; c++) {
        s_t[c * TPAD + tid] = s[c];
        s_t[(8 + c) * TPAD + tid] = q[c];
    }
    __syncthreads();
    // warp w reduces channels 2w and 2w+1 (coalesced LDS.128 rows)
    {
        int w = tid >> 5, lane = tid & 31;
#pragma unroll
        for (int h = 0; h < 2; h++) {
            int c = 2 * w + h;
            const float4* row = (const float4*)(s_t + c * TPAD);
            float4 a = row[lane];
            float4 b = row[lane + 32];
            float p = ((a.x + a.y) + (a.z + a.w)) + ((b.x + b.y) + (b.z + b.w));
#pragma unroll
            for (int o = 16; o > 0; o >>= 1)
                p += __shfl_xor_sync(0xffffffffu, p, o);
            if (lane == 0) g_partials[blockIdx.x * 16 + c] = p;
        }
    }

    // ---- ticket: last block folds ----
    __shared__ unsigned int s_last;
    __threadfence();
    if (tid == 0) s_last = (atomicAdd(&g_ticket, 1u) == (unsigned)(gridDim.x - 1));
    __syncthreads();
    if (!s_last) return;

    __shared__ float s1[256];
    __shared__ float totals[16];
    __shared__ float scale[8], shift[8];
    {   // 16 cols x 16 chunks of 64, 8 independent accumulators per thread
        int col = tid & 15, chunk = tid >> 4;
        const float* p = g_partials + (chunk * 64) * 16 + col;
        float a0 = 0, a1 = 0, a2 = 0, a3 = 0, a4 = 0, a5 = 0, a6 = 0, a7 = 0;
#pragma unroll
        for (int b = 0; b < 64; b += 8) {
            a0 += p[(b + 0) * 16]; a1 += p[(b + 1) * 16];
            a2 += p[(b + 2) * 16]; a3 += p[(b + 3) * 16];
            a4 += p[(b + 4) * 16]; a5 += p[(b + 5) * 16];
            a6 += p[(b + 6) * 16]; a7 += p[(b + 7) * 16];
        }
        s1[col * 16 + chunk] = ((a0 + a1) + (a2 + a3)) + ((a4 + a5) + (a6 + a7));
    }
    __syncthreads();
    if (tid < 16) {
        float acc = 0.0f;
#pragma unroll
        for (int k = 0; k < 16; k++) acc += s1[tid * 16 + k];
        totals[tid] = acc;
    }
    __syncthreads();
    if (tid < 8) {
        float mu = totals[tid] * invB;
        float var = totals[8 + tid] * invB - mu * mu;
        float sc = bn_g[tid] * rsqrtf(var + 1e-5f);
        scale[tid] = sc;
        shift[tid] = bn_b[tid] - mu * sc;
    }
    __syncthreads();

    // folded first layer, layout B
    if (tid < 16) {
        float v = b_fm[tid];
#pragma unroll
        for (int i = 0; i < 8; i++) v += shift[i] * w_fm[i * 16 + tid];
        g_w[FM_B + tid] = make_float2(v, v);
    }
    if (tid < 128) {
        int j = tid >> 3, i = tid & 7;
        float v = scale[i] * w_fm[i * 16 + j];
        g_w[FM_W + j * 8 + i] = make_float2(v, v);
    }
    for (int idx = tid; idx < 256; idx += NT_STATS) { // c1 16->16
        int j = idx >> 4, i = idx & 15;
        float v = w_c1[i * 16 + j];
        g_w[C1_W + j * 16 + i] = make_float2(v, v);
    }
    if (tid < 16) { float v = b_c1[tid]; g_w[C1_B + tid] = make_float2(v, v); }
    for (int idx = tid; idx < 192; idx += NT_STATS) { // p1 16->12
        int j = idx >> 4, i = idx & 15;
        float v = w_p1[i * 12 + j];
        g_w[P1_W + j * 16 + i] = make_float2(v, v);
    }
    if (tid < 12) { float v = b_p1[tid]; g_w[P1_B + tid] = make_float2(v, v); }
    if (tid < 96) {                                    // c2 12->8
        int j = tid / 12, i = tid % 12;
        float v = w_c2[i * 8 + j];
        g_w[C2_W + j * 12 + i] = make_float2(v, v);
    }
    if (tid < 8) { float v = b_c2[tid]; g_w[C2_B + tid] = make_float2(v, v); }
    if (tid < 32) {                                    // p2 8->4
        int j = tid >> 3, i = tid & 7;
        float v = w_p2[i * 4 + j];
        g_w[P2_W + j * 8 + i] = make_float2(v, v);
    }
    if (tid < 4) { float v = b_p2[tid]; g_w[P2_B + tid] = make_float2(v, v); }
    if (tid < 16) {                                    // c3 4->4
        int j = tid >> 2, i = tid & 3;
        float v = w_c3[i * 4 + j];
        g_w[C3_W + j * 4 + i] = make_float2(v, v);
    }
    if (tid < 4) { float v = b_c3[tid]; g_w[C3_B + tid] = make_float2(v, v); }
    if (tid < 16) {                                    // r 4->4
        int j = tid >> 2, i = tid & 3;
        float v = w_r[i * 4 + j];
        g_w[R_W + j * 4 + i] = make_float2(v, v);
    }
    if (tid < 4) { float v = b_r[tid]; g_w[R_B + tid] = make_float2(v, v); }
    if (tid < 4) { float v = w_h[tid]; g_w[H_W + tid] = make_float2(v, v); }
    if (tid == 0) { float v = b_h[0]; g_w[H_B] = make_float2(v, v); }
    __syncthreads();
    if (tid == 0) g_ticket = 0;                       // reset for next replay
}

// ------------------------------- kernel B: main ----------------------------
__global__ void __launch_bounds__(NT_MAIN, 4) k_main(const float* __restrict__ x,
                                                     float* __restrict__ out,
                                                     int nrows) {
    __shared__ __align__(16) u64 sw[U_TOTAL + 1];
    {
        const u64* gw = (const u64*)g_w;
        for (int i = threadIdx.x; i < U_TOTAL; i += NT_MAIN) sw[i] = gw[i];
    }
    __syncthreads();

    int t = blockIdx.x * NT_MAIN + threadIdx.x;
    long base = (long)t * 4;                          // 4 rows / thread
    if (base >= nrows) return;

    const float4* xv = (const float4*)(x + base * 8);
    float4 r0a = xv[0], r0b = xv[1];
    float4 r1a = xv[2], r1b = xv[3];
    float4 r2a = xv[4], r2b = xv[5];
    float4 r3a = xv[6], r3b = xv[7];

    u64 A0[16], A1[16], B0[16], B1[16];
    A0[0] = pk2(r0a.x, r1a.x); A1[0] = pk2(r2a.x, r3a.x);
    A0[1] = pk2(r0a.y, r1a.y); A1[1] = pk2(r2a.y, r3a.y);
    A0[2] = pk2(r0a.z, r1a.z); A1[2] = pk2(r2a.z, r3a.z);
    A0[3] = pk2(r0a.w, r1a.w); A1[3] = pk2(r2a.w, r3a.w);
    A0[4] = pk2(r0b.x, r1b.x); A1[4] = pk2(r2b.x, r3b.x);
    A0[5] = pk2(r0b.y, r1b.y); A1[5] = pk2(r2b.y, r3b.y);
    A0[6] = pk2(r0b.z, r1b.z); A1[6] = pk2(r2b.z, r3b.z);
    A0[7] = pk2(r0b.w, r1b.w); A1[7] = pk2(r2b.w, r3b.w);

    layer2P<8, 16, FM_B, FM_W, true>(sw, A0, A1, B0, B1);   // feature_map
    layer2P<16, 16, C1_B, C1_W, true>(sw, B0, B1, A0, A1);  // conv1
    layer2P<16, 12, P1_B, P1_W, true>(sw, A0, A1, B0, B1);  // pool1
    layer2P<12, 8, C2_B, C2_W, true>(sw, B0, B1, A0, A1);   // conv2
    layer2P<8, 4, P2_B, P2_W, true>(sw, A0, A1, B0, B1);    // pool2
    layer2P<4, 4, C3_B, C3_W, true>(sw, B0, B1, A0, A1);    // conv3
    layer2P<4, 4, R_B, R_W, false>(sw, A0, A1, B0, B1);     // residual pre-relu
#pragma unroll
    for (int j = 0; j < 4; j++) {
        A0[j] = fadd2(A0[j], relu2(B0[j]));
        A1[j] = fadd2(A1[j], relu2(B1[j]));
    }

    // head [4->1], sigmoid(z) = 0.5*tanh(0.5z)+0.5
    u64 acc0 = sw[H_B], acc1 = acc0;
#pragma unroll
    for (int i = 0; i < 4; i++) {
        u64 w = sw[H_W + i];
        acc0 = ffma2(A0[i], w, acc0);
        acc1 = ffma2(A1[i], w, acc1);
    }
    float z0, z1, z2, z3;
    upk2(acc0, z0, z1);
    upk2(acc1, z2, z3);
    float4 o;
    o.x = fmaf(0.5f, tanh_ap(0.5f * z0), 0.5f);
    o.y = fmaf(0.5f, tanh_ap(0.5f * z1), 0.5f);
    o.z = fmaf(0.5f, tanh_ap(0.5f * z2), 0.5f);
    o.w = fmaf(0.5f, tanh_ap(0.5f * z3), 0.5f);
    ((float4*)out)[t] = o;
}

// ------------------------------- launch ------------------------------------
extern "C" void kernel_launch(void* const* d_in, const int* in_sizes, int n_in,
                              void* d_out, int out_size) {
    const float* x    = (const float*)d_in[0];
    const float* bn_g = (const float*)d_in[1];
    const float* bn_b = (const float*)d_in[2];
    const float* w_fm = (const float*)d_in[3];
    const float* b_fm = (const float*)d_in[4];
    const float* w_c1 = (const float*)d_in[5];
    const float* b_c1 = (const float*)d_in[6];
    const float* w_p1 = (const float*)d_in[7];
    const float* b_p1 = (const float*)d_in[8];
    const float* w_c2 = (const float*)d_in[9];
    const float* b_c2 = (const float*)d_in[10];
    const float* w_p2 = (const float*)d_in[11];
    const float* b_p2 = (const float*)d_in[12];
    const float* w_c3 = (const float*)d_in[13];
    const float* b_c3 = (const float*)d_in[14];
    const float* w_r  = (const float*)d_in[15];
    const float* b_r  = (const float*)d_in[16];
    const float* w_h  = (const float*)d_in[17];
    const float* b_h  = (const float*)d_in[18];
    float* out = (float*)d_out;

    int nrows = in_sizes[0] / 8;                      // 1048576

    k_statsfold<<<NBLK_STATS, NT_STATS>>>(x, bn_g, bn_b, w_fm, b_fm,
                                          w_c1, b_c1, w_p1, b_p1, w_c2, b_c2,
                                          w_p2, b_p2, w_c3, b_c3, w_r, b_r,
                                          w_h, b_h, 1.0f / (float)nrows, nrows);
    k_main<<<(nrows / 4) / NT_MAIN, NT_MAIN>>>(x, out, nrows);
}

// round 9
// speedup vs baseline: 11.2360x; 2.0653x over previous
#include <cuda_runtime.h>
#include <cuda_bf16.h>

// ---------------------------------------------------------------------------
// QCNNHybrid R8:
//  k_stats : cp.async.bulk 32KB/block -> SMEM (no LDG issue floor), reduce
//            via SMEM transpose (10 SHFL/thread, not 80).
//  k_fold  : 1 block; reduce partials, fold BN into layer-1, write g_w.
//  memcpy  : g_w -> __constant__ c_w (graph-capturable D2D memcpy node).
//  k_main  : R4 core (2 packs / 4 rows per thread, natural regs); weights
//            from __constant__ -> uniform LDCU path, L1 freed for x loads.
// ---------------------------------------------------------------------------

#define NBLK_STATS 1024
#define NT_STATS   256
#define NT_MAIN    128

__device__ float g_partials[NBLK_STATS * 16];

// layout B (u64 units): per layer [bias x DOUT][weights j-major: DOUT x DIN]
#define FM_B 0
#define FM_W 16     // 16 + 128 = 144
#define C1_B 144
#define C1_W 160    // + 256 = 416
#define P1_B 416
#define P1_W 428    // + 192 = 620
#define C2_B 620
#define C2_W 628    // + 96 = 724
#define P2_B 724
#define P2_W 728    // + 32 = 760
#define C3_B 760
#define C3_W 764    // + 16 = 780
#define R_B  780
#define R_W  784    // + 16 = 800
#define H_B  800
#define H_W  801    // + 4 = 805
#define U_TOTAL 805
__device__ float2 g_w[U_TOTAL];
__constant__ __align__(16) float2 c_w[U_TOTAL + 1];

typedef unsigned long long u64;

// ------------------------------- f32x2 helpers -----------------------------
__device__ __forceinline__ u64 pk2(float a, float b) {
    u64 r;
    asm("mov.b64 %0,{%1,%2};" : "=l"(r) : "f"(a), "f"(b));
    return r;
}
__device__ __forceinline__ void upk2(u64 v, float& a, float& b) {
    asm("mov.b64 {%0,%1},%2;" : "=f"(a), "=f"(b) : "l"(v));
}
__device__ __forceinline__ u64 ffma2(u64 a, u64 b, u64 c) {
    u64 d;
    asm("fma.rn.f32x2 %0,%1,%2,%3;" : "=l"(d) : "l"(a), "l"(b), "l"(c));
    return d;
}
__device__ __forceinline__ u64 fadd2(u64 a, u64 b) {
    u64 d;
    asm("add.rn.f32x2 %0,%1,%2;" : "=l"(d) : "l"(a), "l"(b));
    return d;
}
__device__ __forceinline__ float tanh_ap(float x) {
    float y;
    asm("tanh.approx.f32 %0,%1;" : "=f"(y) : "f"(x));
    return y;
}
__device__ __forceinline__ u64 tanh2(u64 v) {
    float a, b;
    upk2(v, a, b);
    return pk2(tanh_ap(a), tanh_ap(b));
}
__device__ __forceinline__ u64 relu2(u64 v) {
    float a, b;
    upk2(v, a, b);
    return pk2(fmaxf(a, 0.0f), fmaxf(b, 0.0f));
}

// dense layer on two packs (4 rows); weights from __constant__ (uniform path)
template <int DIN, int DOUT, int BB, int WB, bool ACT>
__device__ __forceinline__ void layer2C(const u64* __restrict__ a0,
                                        const u64* __restrict__ a1,
                                        u64* __restrict__ o0,
                                        u64* __restrict__ o1) {
    const u64* cw = (const u64*)c_w;
#pragma unroll
    for (int j = 0; j < DOUT; j++) {
        u64 acc0 = cw[BB + j];                        // duplicated bias
        u64 acc1 = acc0;
#pragma unroll
        for (int i = 0; i < DIN; i++) {
            u64 w = cw[WB + j * DIN + i];
            acc0 = ffma2(a0[i], w, acc0);
            acc1 = ffma2(a1[i], w, acc1);
        }
        if (ACT) { acc0 = tanh2(acc0); acc1 = tanh2(acc1); }
        o0[j] = acc0;
        o1[j] = acc1;
    }
}

// ------------------------------- kernel A: stats ---------------------------
// 1024 blocks x 256 thr; each block bulk-copies 1024 rows (32KB) into SMEM,
// reduces 4 rows/thread, then SMEM-transpose reduction -> 16 partials.
__global__ void __launch_bounds__(NT_STATS) k_stats(const float* __restrict__ x) {
    __shared__ __align__(16) float s_buf[8192];       // 32KB data, reused
    __shared__ __align__(8) unsigned long long s_mbar;
    int tid = threadIdx.x;

    unsigned mb = (unsigned)__cvta_generic_to_shared(&s_mbar);
    unsigned sb = (unsigned)__cvta_generic_to_shared(s_buf);
    const unsigned CHUNK = 32768u;
    if (tid == 0) {
        asm volatile("mbarrier.init.shared.b64 [%0], 1;" :: "r"(mb) : "memory");
        asm volatile("fence.proxy.async.shared::cta;" ::: "memory");
        asm volatile("mbarrier.arrive.expect_tx.shared.b64 _, [%0], %1;"
                     :: "r"(mb), "r"(CHUNK) : "memory");
        const char* src = (const char*)x + (size_t)blockIdx.x * CHUNK;
        asm volatile(
            "cp.async.bulk.shared::cluster.global.mbarrier::complete_tx::bytes "
            "[%0], [%1], %2, [%3];"
            :: "r"(sb), "l"(src), "r"(CHUNK), "r"(mb) : "memory");
    }
    __syncthreads();
    asm volatile(
        "{\n\t"
        ".reg .pred p;\n\t"
        "WAITS_%=:\n\t"
        "mbarrier.try_wait.parity.acquire.cta.shared::cta.b64 p, [%0], 0;\n\t"
        "@!p bra WAITS_%=;\n\t"
        "}"
        :: "r"(mb) : "memory");

    // reduce 4 strided rows/thread (row = tid + k*256): modest bank conflicts
    float s[8], q[8];
#pragma unroll
    for (int c = 0; c < 8; c++) { s[c] = 0.0f; q[c] = 0.0f; }
    const float4* sv = (const float4*)s_buf;
#pragma unroll
    for (int k = 0; k < 4; k++) {
        float4 a = sv[(tid + k * 256) * 2];
        float4 b = sv[(tid + k * 256) * 2 + 1];
        s[0] += a.x; q[0] = fmaf(a.x, a.x, q[0]);
        s[1] += a.y; q[1] = fmaf(a.y, a.y, q[1]);
        s[2] += a.z; q[2] = fmaf(a.z, a.z, q[2]);
        s[3] += a.w; q[3] = fmaf(a.w, a.w, q[3]);
        s[4] += b.x; q[4] = fmaf(b.x, b.x, q[4]);
        s[5] += b.y; q[5] = fmaf(b.y, b.y, q[5]);
        s[6] += b.z; q[6] = fmaf(b.z, b.z, q[6]);
        s[7] += b.w; q[7] = fmaf(b.w, b.w, q[7]);
    }
    __syncthreads();                                   // data consumed
    // transpose into channel-major (reuse s_buf): row len 264 (pad), 16 rows
#pragma unroll
    for (int c = 0; c < 8; c++) {
        s_buf[c * 264 + tid] = s[c];
        s_buf[(8 + c) * 264 + tid] = q[c];
    }
    __syncthreads();
    // warp w reduces channels 2w, 2w+1 (coalesced reads, 5 SHFL each)
    {
        int w = tid >> 5, lane = tid & 31;
#pragma unroll
        for (int h = 0; h < 2; h++) {
            int c = 2 * w + h;
            const float4* row = (const float4*)(s_buf + c * 264);
            float4 a = row[lane];
            float4 b = row[lane + 32];
            float p = ((a.x + a.y) + (a.z + a.w)) + ((b.x + b.y) + (b.z + b.w));
#pragma unroll
            for (int o = 16; o > 0; o >>= 1)
                p += __shfl_xor_sync(0xffffffffu, p, o);
            if (lane == 0) g_partials[blockIdx.x * 16 + c] = p;
        }
    }
}

// ------------------------------- kernel B: fold ----------------------------
__global__ void __launch_bounds__(256) k_fold(
    const float* __restrict__ bn_g, const float* __restrict__ bn_b,
    const float* __restrict__ w_fm, const float* __restrict__ b_fm,
    const float* __restrict__ w_c1, const float* __restrict__ b_c1,
    const float* __restrict__ w_p1, const float* __restrict__ b_p1,
    const float* __restrict__ w_c2, const float* __restrict__ b_c2,
    const float* __restrict__ w_p2, const float* __restrict__ b_p2,
    const float* __restrict__ w_c3, const float* __restrict__ b_c3,
    const float* __restrict__ w_r,  const float* __restrict__ b_r,
    const float* __restrict__ w_h,  const float* __restrict__ b_h,
    float invB) {
    int tid = threadIdx.x;
    __shared__ float s1[256];
    __shared__ float totals[16];
    __shared__ float scale[8], shift[8];
    {   // 16 cols x 16 chunks of 64; 8 independent accumulators (MLP)
        int col = tid & 15, chunk = tid >> 4;
        const float* p = g_partials + (chunk * 64) * 16 + col;
        float a0 = 0, a1 = 0, a2 = 0, a3 = 0, a4 = 0, a5 = 0, a6 = 0, a7 = 0;
#pragma unroll
        for (int b = 0; b < 64; b += 8) {
            a0 += p[(b + 0) * 16]; a1 += p[(b + 1) * 16];
            a2 += p[(b + 2) * 16]; a3 += p[(b + 3) * 16];
            a4 += p[(b + 4) * 16]; a5 += p[(b + 5) * 16];
            a6 += p[(b + 6) * 16]; a7 += p[(b + 7) * 16];
        }
        s1[col * 16 + chunk] = ((a0 + a1) + (a2 + a3)) + ((a4 + a5) + (a6 + a7));
    }
    __syncthreads();
    if (tid < 16) {
        float acc = 0.0f;
#pragma unroll
        for (int k = 0; k < 16; k++) acc += s1[tid * 16 + k];
        totals[tid] = acc;
    }
    __syncthreads();
    if (tid < 8) {
        float mu = totals[tid] * invB;
        float var = totals[8 + tid] * invB - mu * mu;
        float sc = bn_g[tid] * rsqrtf(var + 1e-5f);
        scale[tid] = sc;
        shift[tid] = bn_b[tid] - mu * sc;
    }
    __syncthreads();

    // folded first layer, layout B
    if (tid < 16) {
        float v = b_fm[tid];
#pragma unroll
        for (int i = 0; i < 8; i++) v += shift[i] * w_fm[i * 16 + tid];
        g_w[FM_B + tid] = make_float2(v, v);
    }
    if (tid < 128) {
        int j = tid >> 3, i = tid & 7;
        float v = scale[i] * w_fm[i * 16 + j];
        g_w[FM_W + j * 8 + i] = make_float2(v, v);
    }
    for (int idx = tid; idx < 256; idx += 256) {       // c1 16->16
        int j = idx >> 4, i = idx & 15;
        float v = w_c1[i * 16 + j];
        g_w[C1_W + j * 16 + i] = make_float2(v, v);
    }
    if (tid < 16) { float v = b_c1[tid]; g_w[C1_B + tid] = make_float2(v, v); }
    if (tid < 192) {                                   // p1 16->12
        int j = tid >> 4, i = tid & 15;
        float v = w_p1[i * 12 + j];
        g_w[P1_W + j * 16 + i] = make_float2(v, v);
    }
    if (tid < 12) { float v = b_p1[tid]; g_w[P1_B + tid] = make_float2(v, v); }
    if (tid < 96) {                                    // c2 12->8
        int j = tid / 12, i = tid % 12;
        float v = w_c2[i * 8 + j];
        g_w[C2_W + j * 12 + i] = make_float2(v, v);
    }
    if (tid < 8) { float v = b_c2[tid]; g_w[C2_B + tid] = make_float2(v, v); }
    if (tid < 32) {                                    // p2 8->4
        int j = tid >> 3, i = tid & 7;
        float v = w_p2[i * 4 + j];
        g_w[P2_W + j * 8 + i] = make_float2(v, v);
    }
    if (tid < 4) { float v = b_p2[tid]; g_w[P2_B + tid] = make_float2(v, v); }
    if (tid < 16) {                                    // c3 4->4
        int j = tid >> 2, i = tid & 3;
        float v = w_c3[i * 4 + j];
        g_w[C3_W + j * 4 + i] = make_float2(v, v);
    }
    if (tid < 4) { float v = b_c3[tid]; g_w[C3_B + tid] = make_float2(v, v); }
    if (tid < 16) {                                    // r 4->4
        int j = tid >> 2, i = tid & 3;
        float v = w_r[i * 4 + j];
        g_w[R_W + j * 4 + i] = make_float2(v, v);
    }
    if (tid < 4) { float v = b_r[tid]; g_w[R_B + tid] = make_float2(v, v); }
    if (tid < 4) { float v = w_h[tid]; g_w[H_W + tid] = make_float2(v, v); }
    if (tid == 0) { float v = b_h[0]; g_w[H_B] = make_float2(v, v); }
}

// ------------------------------- kernel C: main ----------------------------
__global__ void __launch_bounds__(NT_MAIN) k_main(const float* __restrict__ x,
                                                  float* __restrict__ out,
                                                  int nrows) {
    int t = blockIdx.x * NT_MAIN + threadIdx.x;
    long base = (long)t * 4;                          // 4 rows / thread
    if (base >= nrows) return;

    const float4* xv = (const float4*)(x + base * 8);
    float4 r0a = xv[0], r0b = xv[1];
    float4 r1a = xv[2], r1b = xv[3];
    float4 r2a = xv[4], r2b = xv[5];
    float4 r3a = xv[6], r3b = xv[7];

    u64 A0[16], A1[16], B0[16], B1[16];
    A0[0] = pk2(r0a.x, r1a.x); A1[0] = pk2(r2a.x, r3a.x);
    A0[1] = pk2(r0a.y, r1a.y); A1[1] = pk2(r2a.y, r3a.y);
    A0[2] = pk2(r0a.z, r1a.z); A1[2] = pk2(r2a.z, r3a.z);
    A0[3] = pk2(r0a.w, r1a.w); A1[3] = pk2(r2a.w, r3a.w);
    A0[4] = pk2(r0b.x, r1b.x); A1[4] = pk2(r2b.x, r3b.x);
    A0[5] = pk2(r0b.y, r1b.y); A1[5] = pk2(r2b.y, r3b.y);
    A0[6] = pk2(r0b.z, r1b.z); A1[6] = pk2(r2b.z, r3b.z);
    A0[7] = pk2(r0b.w, r1b.w); A1[7] = pk2(r2b.w, r3b.w);

    layer2C<8, 16, FM_B, FM_W, true>(A0, A1, B0, B1);   // feature_map
    layer2C<16, 16, C1_B, C1_W, true>(B0, B1, A0, A1);  // conv1
    layer2C<16, 12, P1_B, P1_W, true>(A0, A1, B0, B1);  // pool1
    layer2C<12, 8, C2_B, C2_W, true>(B0, B1, A0, A1);   // conv2
    layer2C<8, 4, P2_B, P2_W, true>(A0, A1, B0, B1);    // pool2
    layer2C<4, 4, C3_B, C3_W, true>(B0, B1, A0, A1);    // conv3
    layer2C<4, 4, R_B, R_W, false>(A0, A1, B0, B1);     // residual pre-relu
#pragma unroll
    for (int j = 0; j < 4; j++) {
        A0[j] = fadd2(A0[j], relu2(B0[j]));
        A1[j] = fadd2(A1[j], relu2(B1[j]));
    }

    // head [4->1], sigmoid(z) = 0.5*tanh(0.5z)+0.5
    const u64* cw = (const u64*)c_w;
    u64 acc0 = cw[H_B], acc1 = acc0;
#pragma unroll
    for (int i = 0; i < 4; i++) {
        u64 w = cw[H_W + i];
        acc0 = ffma2(A0[i], w, acc0);
        acc1 = ffma2(A1[i], w, acc1);
    }
    float z0, z1, z2, z3;
    upk2(acc0, z0, z1);
    upk2(acc1, z2, z3);
    float4 o;
    o.x = fmaf(0.5f, tanh_ap(0.5f * z0), 0.5f);
    o.y = fmaf(0.5f, tanh_ap(0.5f * z1), 0.5f);
    o.z = fmaf(0.5f, tanh_ap(0.5f * z2), 0.5f);
    o.w = fmaf(0.5f, tanh_ap(0.5f * z3), 0.5f);
    ((float4*)out)[t] = o;
}

// ------------------------------- launch ------------------------------------
extern "C" void kernel_launch(void* const* d_in, const int* in_sizes, int n_in,
                              void* d_out, int out_size) {
    const float* x    = (const float*)d_in[0];
    const float* bn_g = (const float*)d_in[1];
    const float* bn_b = (const float*)d_in[2];
    const float* w_fm = (const float*)d_in[3];
    const float* b_fm = (const float*)d_in[4];
    const float* w_c1 = (const float*)d_in[5];
    const float* b_c1 = (const float*)d_in[6];
    const float* w_p1 = (const float*)d_in[7];
    const float* b_p1 = (const float*)d_in[8];
    const float* w_c2 = (const float*)d_in[9];
    const float* b_c2 = (const float*)d_in[10];
    const float* w_p2 = (const float*)d_in[11];
    const float* b_p2 = (const float*)d_in[12];
    const float* w_c3 = (const float*)d_in[13];
    const float* b_c3 = (const float*)d_in[14];
    const float* w_r  = (const float*)d_in[15];
    const float* b_r  = (const float*)d_in[16];
    const float* w_h  = (const float*)d_in[17];
    const float* b_h  = (const float*)d_in[18];
    float* out = (float*)d_out;

    int nrows = in_sizes[0] / 8;                      // 1048576

    k_stats<<<NBLK_STATS, NT_STATS>>>(x);
    k_fold<<<1, 256>>>(bn_g, bn_b, w_fm, b_fm, w_c1, b_c1, w_p1, b_p1,
                       w_c2, b_c2, w_p2, b_p2, w_c3, b_c3, w_r, b_r,
                       w_h, b_h, 1.0f / (float)nrows);
    // publish folded params to constant memory (D2D memcpy, graph-capturable)
    void* gw_addr = nullptr;
    cudaGetSymbolAddress(&gw_addr, g_w);
    cudaMemcpyToSymbolAsync(c_w, gw_addr, U_TOTAL * sizeof(float2), 0,
                            cudaMemcpyDeviceToDevice, 0);
    k_main<<<(nrows / 4) / NT_MAIN, NT_MAIN>>>(x, out, nrows);
}